// round 15
// baseline (speedup 1.0000x reference)
#include <cuda_runtime.h>
#include <cuda_bf16.h>
#include <cuda_fp16.h>
#include <math.h>
#include <stdint.h>

// ---- model dims ----
#define SQ   2048
#define HID  1024
#define NHEAD 16
#define HD   64
#define FFD  4096
#define NEXP 8
#define TOPK 2
#define VOC  32000
#define NLAY 2

typedef unsigned long long u64;

// ---------------- f32x2 helpers ----------------
__device__ __forceinline__ u64 pk2(float lo, float hi) {
    u64 r; asm("mov.b64 %0, {%1,%2};" : "=l"(r) : "f"(lo), "f"(hi)); return r;
}
__device__ __forceinline__ void upk2(u64 v, float& lo, float& hi) {
    asm("mov.b64 {%0,%1}, %2;" : "=f"(lo), "=f"(hi) : "l"(v));
}
__device__ __forceinline__ u64 ffma2(u64 a, u64 b, u64 c) {
    u64 d; asm("fma.rn.f32x2 %0, %1, %2, %3;" : "=l"(d) : "l"(a), "l"(b), "l"(c)); return d;
}
__device__ __forceinline__ u64 fmul2(u64 a, u64 b) {
    u64 d; asm("mul.rn.f32x2 %0, %1, %2;" : "=l"(d) : "l"(a), "l"(b)); return d;
}

// ---------------- bf16 / fp16 splits ----------------
__device__ __forceinline__ void bfsplit2(float x0, float x1, uint32_t& h, uint32_t& l) {
    __nv_bfloat16 h0 = __float2bfloat16(x0);
    __nv_bfloat16 h1 = __float2bfloat16(x1);
    float r0 = x0 - __bfloat162float(h0);
    float r1 = x1 - __bfloat162float(h1);
    __nv_bfloat16 l0 = __float2bfloat16(r0);
    __nv_bfloat16 l1 = __float2bfloat16(r1);
    h = ((uint32_t)__bfloat16_as_ushort(h1) << 16) | (uint32_t)__bfloat16_as_ushort(h0);
    l = ((uint32_t)__bfloat16_as_ushort(l1) << 16) | (uint32_t)__bfloat16_as_ushort(l0);
}
__device__ __forceinline__ void hsplit2(float x0, float x1, uint32_t& h, uint32_t& l) {
    __half h0 = __float2half_rn(x0);
    __half h1 = __float2half_rn(x1);
    float r0 = x0 - __half2float(h0);
    float r1 = x1 - __half2float(h1);
    __half l0 = __float2half_rn(r0);
    __half l1 = __float2half_rn(r1);
    h = ((uint32_t)__half_as_ushort(h1) << 16) | (uint32_t)__half_as_ushort(h0);
    l = ((uint32_t)__half_as_ushort(l1) << 16) | (uint32_t)__half_as_ushort(l0);
}
__device__ __forceinline__ void mma_bf16(float& d0, float& d1, float& d2, float& d3,
                                         uint32_t a0, uint32_t a1, uint32_t a2, uint32_t a3,
                                         uint32_t b0, uint32_t b1) {
    asm volatile(
        "mma.sync.aligned.m16n8k16.row.col.f32.bf16.bf16.f32 "
        "{%0,%1,%2,%3},{%4,%5,%6,%7},{%8,%9},{%0,%1,%2,%3};"
        : "+f"(d0), "+f"(d1), "+f"(d2), "+f"(d3)
        : "r"(a0), "r"(a1), "r"(a2), "r"(a3), "r"(b0), "r"(b1));
}
__device__ __forceinline__ void mma_f16(float& d0, float& d1, float& d2, float& d3,
                                        uint32_t a0, uint32_t a1, uint32_t a2, uint32_t a3,
                                        uint32_t b0, uint32_t b1) {
    asm volatile(
        "mma.sync.aligned.m16n8k16.row.col.f32.f16.f16.f32 "
        "{%0,%1,%2,%3},{%4,%5,%6,%7},{%8,%9},{%0,%1,%2,%3};"
        : "+f"(d0), "+f"(d1), "+f"(d2), "+f"(d3)
        : "r"(a0), "r"(a1), "r"(a2), "r"(a3), "r"(b0), "r"(b1));
}

// ---------------- cp.async ----------------
__device__ __forceinline__ uint32_t s2u(const void* p) {
    uint32_t a;
    asm("{ .reg .u64 t; cvta.to.shared.u64 t, %1; cvt.u32.u64 %0, t; }" : "=r"(a) : "l"(p));
    return a;
}
__device__ __forceinline__ void cpa16(uint32_t dst, const void* src) {
    asm volatile("cp.async.cg.shared.global [%0], [%1], 16;" :: "r"(dst), "l"(src));
}
#define CP_COMMIT() asm volatile("cp.async.commit_group;" ::: "memory")
#define CP_WAIT(n)  asm volatile("cp.async.wait_group %0;" :: "n"(n) : "memory")

// ---- scratch (device globals) ----
__device__ float g_x   [SQ * HID];
__device__ float g_ln  [SQ * HID];
__device__ float g_qkv [SQ * 3 * HID];
__device__ float g_out2[SQ * TOPK * HID];
__device__ float g_slotw[SQ * TOPK];
__device__ int   g_elist[NEXP * SQ];
__device__ int   g_ecnt [NEXP];

// pre-split 16-bit-pair planes (hi/lo), all K-major [rows][K/2] u32
__device__ uint32_t g_wqkvh[NLAY * 3 * HID * HID / 2], g_wqkvl[NLAY * 3 * HID * HID / 2];
__device__ uint32_t g_woh  [NLAY * HID * HID / 2],     g_wol  [NLAY * HID * HID / 2];
__device__ uint32_t g_w1h  [NLAY * NEXP * FFD * HID / 2], g_w1l[NLAY * NEXP * FFD * HID / 2];
__device__ uint32_t g_w2h  [NLAY * NEXP * HID * FFD / 2], g_w2l[NLAY * NEXP * HID * FFD / 2];
__device__ uint32_t g_tokh [VOC * HID / 2];              // fp16 (lm_head B, single plane)
__device__ uint32_t g_lnh  [SQ * HID / 2],             g_lnl  [SQ * HID / 2];
__device__ uint32_t g_attnh[SQ * HID / 2],             g_attnl[SQ * HID / 2];
__device__ uint32_t g_hidh [SQ * TOPK * FFD / 2],      g_hidl [SQ * TOPK * FFD / 2];

// ---------------------------------------------------------------------------
__global__ void embed_k(const int* __restrict__ idx,
                        const float* __restrict__ tok,
                        const float* __restrict__ pos) {
    int s = blockIdx.x;
    int row = idx[s];
    for (int h = threadIdx.x; h < HID; h += blockDim.x)
        g_x[s * HID + h] = tok[(long)row * HID + h] + pos[(long)s * HID + h];
}

// ---------------------------------------------------------------------------
__global__ void conv_pack_k(const float* __restrict__ src,
                            uint32_t* __restrict__ dh, uint32_t* __restrict__ dl,
                            long total) {
    long i = (long)blockIdx.x * 256 + threadIdx.x;
    if (i >= total) return;
    float2 v = ((const float2*)src)[i];
    uint32_t h, l;
    bfsplit2(v.x, v.y, h, l);
    dh[i] = h; dl[i] = l;
}

// fp16 single-plane pack (lm_head B)
__global__ void conv_pack_h_k(const float* __restrict__ src,
                              uint32_t* __restrict__ dh, long total) {
    long i = (long)blockIdx.x * 256 + threadIdx.x;
    if (i >= total) return;
    float2 v = ((const float2*)src)[i];
    __half h0 = __float2half_rn(v.x), h1 = __float2half_rn(v.y);
    dh[i] = ((uint32_t)__half_as_ushort(h1) << 16) | (uint32_t)__half_as_ushort(h0);
}

// transpose+pack: src f32 [Kd,Nd] per matrix -> bf16 planes [Nd,Kd/2]
__global__ void conv_tr_k(const float* __restrict__ src,
                          uint32_t* __restrict__ dh, uint32_t* __restrict__ dl,
                          int Kd, int Nd, long msi, long mso) {
    __shared__ float sm[64][33];
    int z = blockIdx.z;
    int k0 = blockIdx.x * 64, n0 = blockIdx.y * 32;
    int t = threadIdx.x;
    const float* S = src + (long)z * msi;
    int tk = t >> 5, tn = t & 31;
    #pragma unroll
    for (int i = 0; i < 8; i++)
        sm[tk + 8 * i][tn] = S[(long)(k0 + tk + 8 * i) * Nd + n0 + tn];
    __syncthreads();
    int kk = t & 31, nl = t >> 5;
    #pragma unroll
    for (int j = 0; j < 4; j++) {
        int n = nl + 8 * j;
        uint32_t h, l;
        bfsplit2(sm[2 * kk][n], sm[2 * kk + 1][n], h, l);
        long o = (long)z * mso + (long)(n0 + n) * (Kd >> 1) + (k0 >> 1) + kk;
        dh[o] = h; dl[o] = l;
    }
}

// ---------------------------------------------------------------------------
// LayerNorm; fp16mode=1 emits fp16 split planes (for lm_head), else bf16.
__global__ void ln_k(const float* __restrict__ in, float* __restrict__ outf,
                     uint32_t* __restrict__ oh, uint32_t* __restrict__ ol,
                     const float* __restrict__ g, const float* __restrict__ b,
                     int fp16mode) {
    int s = blockIdx.x, t = threadIdx.x;
    __shared__ float red[256];
    float4 v = ((const float4*)(in + (long)s * HID))[t];
    red[t] = v.x + v.y + v.z + v.w;
    __syncthreads();
    for (int o = 128; o > 0; o >>= 1) { if (t < o) red[t] += red[t + o]; __syncthreads(); }
    float mu = red[0] * (1.0f / HID);
    __syncthreads();
    float dx = v.x - mu, dy = v.y - mu, dz = v.z - mu, dw = v.w - mu;
    red[t] = dx * dx + dy * dy + dz * dz + dw * dw;
    __syncthreads();
    for (int o = 128; o > 0; o >>= 1) { if (t < o) red[t] += red[t + o]; __syncthreads(); }
    float inv = rsqrtf(red[0] * (1.0f / HID) + 1e-5f);
    float4 gg = ((const float4*)g)[t], bb = ((const float4*)b)[t];
    float4 o4;
    o4.x = dx * inv * gg.x + bb.x;
    o4.y = dy * inv * gg.y + bb.y;
    o4.z = dz * inv * gg.z + bb.z;
    o4.w = dw * inv * gg.w + bb.w;
    ((float4*)(outf + (long)s * HID))[t] = o4;
    uint32_t h0, l0, h1, l1;
    if (fp16mode) {
        hsplit2(o4.x, o4.y, h0, l0);
        hsplit2(o4.z, o4.w, h1, l1);
    } else {
        bfsplit2(o4.x, o4.y, h0, l0);
        bfsplit2(o4.z, o4.w, h1, l1);
    }
    long p = (long)s * 512 + 2 * t;
    oh[p] = h0; oh[p + 1] = h1; ol[p] = l0; ol[p + 1] = l1;
}

// ---------------------------------------------------------------------------
// Tensor-core GEMM on pre-split planes, cp.async double-buffered.
// H2T=0: 3-term bf16 (hh+hl+lh). H2T=1: 1-term fp16 (ah·bh only; Al/Bl unused).
#define ASTRIDE 20
#define PLANE   (128 * ASTRIDE)
#define BUFU32  (4 * PLANE)
#define SM_TOT  (2 * BUFU32 * 4)   // 81920 B

template <int H2T>
__global__ void __launch_bounds__(256, 2) bfgemm_k(
        const uint32_t* __restrict__ Ah, const uint32_t* __restrict__ Al, int lda2,
        const uint32_t* __restrict__ Bh_, const uint32_t* __restrict__ Bl_, long strideB,
        const float* __restrict__ bias,
        float* __restrict__ C, int ldc,
        uint32_t* __restrict__ Chi, uint32_t* __restrict__ Clo, int ldc2,
        int M, int N, int K,
        int accum, int gelu, int row_mode,
        const int* __restrict__ elist, const int* __restrict__ ecnt) {
    extern __shared__ uint32_t smem[];
    uint32_t sb = s2u(smem);

    int e = blockIdx.z;
    long eoff = (long)e * strideB;
    int Me = M;
    const int* list = nullptr;
    if (row_mode) { Me = ecnt[e]; list = elist + e * SQ; }
    int m0 = blockIdx.y * 128;
    if (m0 >= Me) return;
    int n0 = blockIdx.x * 128;

    int t = threadIdx.x;
    int lane = t & 31, wid = t >> 5;
    int warp_m = wid >> 2, warp_n = wid & 3;
    int g = lane >> 2, t4 = lane & 3;

    int am = t & 127, seg = t >> 7;
    int lrow = m0 + am;
    const uint32_t* Arh = nullptr;
    const uint32_t* Arl = nullptr;
    if (lrow < Me) {
        long gr;
        if (row_mode == 0) gr = lrow;
        else { int slot = list[lrow]; gr = (row_mode == 1) ? (slot >> 1) : slot; }
        Arh = Ah + gr * (long)lda2;
        Arl = Al + gr * (long)lda2;
    }
    int ldb2 = K >> 1;
    const uint32_t* Brh = Bh_ + eoff + (long)(n0 + am) * ldb2;
    const uint32_t* Brl = H2T ? nullptr : (Bl_ + eoff + (long)(n0 + am) * ldb2);

    int nch = K / 32;

    auto issue = [&](int c, int b) {
        int off = c * 16 + seg * 8;
        uint32_t base = sb + (uint32_t)(b * BUFU32) * 4u;
        uint32_t da = base + (uint32_t)(am * ASTRIDE + seg * 8) * 4u;
        if (Arh) {
            cpa16(da,                    Arh + off);
            cpa16(da + 16,               Arh + off + 4);
            if (!H2T) {
                cpa16(da + PLANE * 4,        Arl + off);
                cpa16(da + PLANE * 4 + 16,   Arl + off + 4);
            }
        }
        uint32_t db = base + (uint32_t)(2 * PLANE + am * ASTRIDE + seg * 8) * 4u;
        cpa16(db,                    Brh + off);
        cpa16(db + 16,               Brh + off + 4);
        if (!H2T) {
            cpa16(db + PLANE * 4,        Brl + off);
            cpa16(db + PLANE * 4 + 16,   Brl + off + 4);
        }
        CP_COMMIT();
    };

    float acc[4][4][4];
    #pragma unroll
    for (int i = 0; i < 4; i++)
        #pragma unroll
        for (int j = 0; j < 4; j++)
            #pragma unroll
            for (int c = 0; c < 4; c++) acc[i][j][c] = 0.f;

    issue(0, 0);
    for (int c = 0; c < nch; c++) {
        int b = c & 1;
        if (c + 1 < nch) { issue(c + 1, b ^ 1); CP_WAIT(1); }
        else             { CP_WAIT(0); }
        __syncthreads();

        const uint32_t* base = smem + b * BUFU32;
        const uint32_t* pah = base + (warp_m * 64) * ASTRIDE;
        const uint32_t* pal = base + PLANE + (warp_m * 64) * ASTRIDE;
        const uint32_t* pbh = base + 2 * PLANE + (warp_n * 32) * ASTRIDE;
        const uint32_t* pbl = base + 3 * PLANE + (warp_n * 32) * ASTRIDE;

        #pragma unroll
        for (int ks = 0; ks < 2; ks++) {
            int kc = ks * 8;
            uint32_t afh[4][4], afl[4][4], bfh[4][2], bfl[4][2];
            #pragma unroll
            for (int mt = 0; mt < 4; mt++) {
                int r0 = (mt * 16 + g) * ASTRIDE + kc + t4;
                int r1 = (mt * 16 + g + 8) * ASTRIDE + kc + t4;
                afh[mt][0] = pah[r0]; afh[mt][1] = pah[r1];
                afh[mt][2] = pah[r0 + 4]; afh[mt][3] = pah[r1 + 4];
                if (!H2T) {
                    afl[mt][0] = pal[r0]; afl[mt][1] = pal[r1];
                    afl[mt][2] = pal[r0 + 4]; afl[mt][3] = pal[r1 + 4];
                }
            }
            #pragma unroll
            for (int nt = 0; nt < 4; nt++) {
                int r = (nt * 8 + g) * ASTRIDE + kc + t4;
                bfh[nt][0] = pbh[r]; bfh[nt][1] = pbh[r + 4];
                if (!H2T) { bfl[nt][0] = pbl[r]; bfl[nt][1] = pbl[r + 4]; }
            }
            #pragma unroll
            for (int mt = 0; mt < 4; mt++)
                #pragma unroll
                for (int nt = 0; nt < 4; nt++) {
                    float* a = acc[mt][nt];
                    if (H2T) {
                        mma_f16(a[0], a[1], a[2], a[3],
                                afh[mt][0], afh[mt][1], afh[mt][2], afh[mt][3],
                                bfh[nt][0], bfh[nt][1]);
                    } else {
                        mma_bf16(a[0], a[1], a[2], a[3],
                                 afh[mt][0], afh[mt][1], afh[mt][2], afh[mt][3],
                                 bfh[nt][0], bfh[nt][1]);
                        mma_bf16(a[0], a[1], a[2], a[3],
                                 afh[mt][0], afh[mt][1], afh[mt][2], afh[mt][3],
                                 bfl[nt][0], bfl[nt][1]);
                        mma_bf16(a[0], a[1], a[2], a[3],
                                 afl[mt][0], afl[mt][1], afl[mt][2], afl[mt][3],
                                 bfh[nt][0], bfh[nt][1]);
                    }
                }
        }
        __syncthreads();
    }

    // ---- epilogue ----
    #pragma unroll
    for (int mt = 0; mt < 4; mt++) {
        int rbase = warp_m * 64 + mt * 16 + g;
        #pragma unroll
        for (int p = 0; p < 2; p++) {
            int lr = m0 + rbase + 8 * p;
            if (lr >= Me) continue;
            long crow = row_mode ? (long)list[lr] : (long)lr;
            if (Chi) {
                long ob = crow * (long)ldc2 + ((n0 + warp_n * 32) >> 1);
                #pragma unroll
                for (int nt = 0; nt < 4; nt++) {
                    int col = nt * 8 + 2 * t4;
                    float v0 = acc[mt][nt][2 * p];
                    float v1 = acc[mt][nt][2 * p + 1];
                    if (gelu) { v0 = v0 * normcdff(v0); v1 = v1 * normcdff(v1); }
                    uint32_t h, l;
                    bfsplit2(v0, v1, h, l);
                    Chi[ob + (col >> 1)] = h;
                    Clo[ob + (col >> 1)] = l;
                }
            } else {
                float* cp = C + crow * (long)ldc + n0 + warp_n * 32;
                const float* bp = bias ? bias + n0 + warp_n * 32 : nullptr;
                #pragma unroll
                for (int nt = 0; nt < 4; nt++) {
                    int col = nt * 8 + 2 * t4;
                    float v0 = acc[mt][nt][2 * p];
                    float v1 = acc[mt][nt][2 * p + 1];
                    if (bp) { v0 += bp[col]; v1 += bp[col + 1]; }
                    if (gelu) { v0 = v0 * normcdff(v0); v1 = v1 * normcdff(v1); }
                    if (accum) { v0 += cp[col]; v1 += cp[col + 1]; }
                    *(float2*)&cp[col] = make_float2(v0, v1);
                }
            }
        }
    }
}

// ---------------------------------------------------------------------------
// Causal flash attention: 256 threads = 64 queries x 4 quarter-threads (16 dims),
// batch-16 online softmax, f32x2 math; writes split planes for the Wo GEMM.
__global__ void attn_k() {
    int h  = blockIdx.y;
    int q0 = blockIdx.x * 64;
    int t  = threadIdx.x;
    int ql = t >> 2, q4 = t & 3;
    int q  = q0 + ql;

    u64 qv2[8];
    {
        const float* qptr = &g_qkv[(long)q * 3072 + h * 64 + q4 * 16];
        #pragma unroll
        for (int i = 0; i < 4; i++) {
            ulonglong2 v = *(const ulonglong2*)&qptr[i * 4];
            qv2[2 * i] = v.x; qv2[2 * i + 1] = v.y;
        }
    }

    float m = -1e30f, l = 0.f;
    u64 acc2[8];
    #pragma unroll
    for (int i = 0; i < 8; i++) acc2[i] = 0ULL;

    __shared__ float Ks[64][64];
    __shared__ float Vs[64][64];

    for (int kt = 0; kt <= q0 + 63; kt += 64) {
        #pragma unroll
        for (int i = t * 4; i < 64 * 64; i += 256 * 4) {
            int kk = i >> 6, d = i & 63;
            *(float4*)&Ks[kk][d] = *(const float4*)&g_qkv[(long)(kt + kk) * 3072 + 1024 + h * 64 + d];
            *(float4*)&Vs[kk][d] = *(const float4*)&g_qkv[(long)(kt + kk) * 3072 + 2048 + h * 64 + d];
        }
        __syncthreads();

        int kmax = q - kt + 1;
        if (kmax > 64) kmax = 64;

        for (int kb = 0; kb < 64; kb += 16) {
            float s[16];
            #pragma unroll
            for (int j = 0; j < 16; j++) {
                const u64* K2 = (const u64*)&Ks[kb + j][q4 * 16];
                u64 p2 = 0ULL;
                #pragma unroll
                for (int i = 0; i < 8; i++) p2 = ffma2(qv2[i], K2[i], p2);
                float lo, hi;
                upk2(p2, lo, hi);
                float p = lo + hi;
                p += __shfl_xor_sync(0xffffffffu, p, 1);
                p += __shfl_xor_sync(0xffffffffu, p, 2);
                s[j] = p * 0.125f;
            }

            int c = kmax - kb; if (c > 16) c = 16;
            if (c <= 0) continue;

            float bm = s[0];
            #pragma unroll
            for (int j = 1; j < 16; j++) if (j < c) bm = fmaxf(bm, s[j]);
            float mn = fmaxf(m, bm);
            float cor = __expf(m - mn);
            m = mn;
            l *= cor;
            u64 cor2 = pk2(cor, cor);
            #pragma unroll
            for (int i = 0; i < 8; i++) acc2[i] = fmul2(acc2[i], cor2);

            #pragma unroll
            for (int j = 0; j < 16; j++) {
                if (j >= c) break;
                float pe = __expf(s[j] - mn);
                l += pe;
                u64 pe2 = pk2(pe, pe);
                const u64* V2 = (const u64*)&Vs[kb + j][q4 * 16];
                #pragma unroll
                for (int i = 0; i < 8; i++) acc2[i] = ffma2(V2[i], pe2, acc2[i]);
            }
        }
        __syncthreads();
    }

    float inv = 1.f / l;
    long pidx = (long)q * 512 + h * 32 + q4 * 8;
    #pragma unroll
    for (int i = 0; i < 8; i++) {
        float lo, hi;
        upk2(acc2[i], lo, hi);
        uint32_t hh, ll;
        bfsplit2(lo * inv, hi * inv, hh, ll);
        g_attnh[pidx + i] = hh;
        g_attnl[pidx + i] = ll;
    }
}

// ---------------------------------------------------------------------------
__global__ void zero_cnt_k() { if (threadIdx.x < NEXP) g_ecnt[threadIdx.x] = 0; }

__global__ void router_k(const float* __restrict__ rw) {
    int tok = blockIdx.x, t = threadIdx.x;   // 128 threads
    __shared__ float sm[NEXP][128];
    __shared__ float logits[NEXP];
    const float* xr = g_ln + (long)tok * HID;

    for (int e = 0; e < NEXP; e++) {
        float s = 0.f;
        for (int j = t; j < HID; j += 128) s += xr[j] * rw[e * HID + j];
        sm[e][t] = s;
    }
    __syncthreads();
    if (t < NEXP) {
        float s = 0.f;
        for (int j = 0; j < 128; j++) s += sm[t][j];
        logits[t] = s;
    }
    __syncthreads();
    if (t == 0) {
        float mx = logits[0];
        for (int e = 1; e < NEXP; e++) mx = fmaxf(mx, logits[e]);
        float p[NEXP], den = 0.f;
        for (int e = 0; e < NEXP; e++) { p[e] = expf(logits[e] - mx); den += p[e]; }
        float idn = 1.f / den;
        for (int e = 0; e < NEXP; e++) p[e] *= idn;
        int i1 = 0;
        for (int e = 1; e < NEXP; e++) if (p[e] > p[i1]) i1 = e;
        int i2 = -1;
        for (int e = 0; e < NEXP; e++) {
            if (e == i1) continue;
            if (i2 < 0 || p[e] > p[i2]) i2 = e;
        }
        g_slotw[tok * 2 + 0] = p[i1];
        g_slotw[tok * 2 + 1] = p[i2];
        int p1 = atomicAdd(&g_ecnt[i1], 1); g_elist[i1 * SQ + p1] = tok * 2 + 0;
        int p2 = atomicAdd(&g_ecnt[i2], 1); g_elist[i2 * SQ + p2] = tok * 2 + 1;
    }
}

// ---------------------------------------------------------------------------
__global__ void combine_k() {
    int tok = blockIdx.x;
    float w0 = g_slotw[tok * 2 + 0];
    float w1 = g_slotw[tok * 2 + 1];
    const float* o0 = g_out2 + (long)(tok * 2 + 0) * HID;
    const float* o1 = g_out2 + (long)(tok * 2 + 1) * HID;
    float* xr = g_x + (long)tok * HID;
    for (int h = threadIdx.x; h < HID; h += blockDim.x)
        xr[h] += w0 * o0[h] + w1 * o1[h];
}

// ---------------------------------------------------------------------------
extern "C" void kernel_launch(void* const* d_in, const int* in_sizes, int n_in,
                              void* d_out, int out_size) {
    const int*   idx  = (const int*)  d_in[0];
    const float* tok  = (const float*)d_in[1];
    const float* pos  = (const float*)d_in[2];
    const float* ln1g = (const float*)d_in[3];
    const float* ln1b = (const float*)d_in[4];
    const float* wqkv = (const float*)d_in[5];
    const float* bqkv = (const float*)d_in[6];
    const float* wo   = (const float*)d_in[7];
    const float* bo   = (const float*)d_in[8];
    const float* ln2g = (const float*)d_in[9];
    const float* ln2b = (const float*)d_in[10];
    const float* rw   = (const float*)d_in[11];
    const float* w1   = (const float*)d_in[12];
    const float* w2   = (const float*)d_in[13];
    const float* lnfg = (const float*)d_in[14];
    const float* lnfb = (const float*)d_in[15];
    float* out = (float*)d_out;

    cudaFuncSetAttribute(bfgemm_k<0>, cudaFuncAttributeMaxDynamicSharedMemorySize, SM_TOT);
    cudaFuncSetAttribute(bfgemm_k<1>, cudaFuncAttributeMaxDynamicSharedMemorySize, SM_TOT);

    void* p_;
    #define SYM(var, sym) cudaGetSymbolAddress(&p_, sym); auto var = p_
    SYM(px_, g_x);        float* px = (float*)px_;
    SYM(pln_, g_ln);      float* pln = (float*)pln_;
    SYM(pqkv_, g_qkv);    float* pqkv = (float*)pqkv_;
    SYM(pout2_, g_out2);  float* pout2 = (float*)pout2_;
    SYM(pel_, g_elist);   const int* pel = (const int*)pel_;
    SYM(pec_, g_ecnt);    const int* pec = (const int*)pec_;
    SYM(pwqkvh_, g_wqkvh); uint32_t* pwqkvh = (uint32_t*)pwqkvh_;
    SYM(pwqkvl_, g_wqkvl); uint32_t* pwqkvl = (uint32_t*)pwqkvl_;
    SYM(pwoh_, g_woh);     uint32_t* pwoh = (uint32_t*)pwoh_;
    SYM(pwol_, g_wol);     uint32_t* pwol = (uint32_t*)pwol_;
    SYM(pw1h_, g_w1h);     uint32_t* pw1h = (uint32_t*)pw1h_;
    SYM(pw1l_, g_w1l);     uint32_t* pw1l = (uint32_t*)pw1l_;
    SYM(pw2h_, g_w2h);     uint32_t* pw2h = (uint32_t*)pw2h_;
    SYM(pw2l_, g_w2l);     uint32_t* pw2l = (uint32_t*)pw2l_;
    SYM(ptokh_, g_tokh);   uint32_t* ptokh = (uint32_t*)ptokh_;
    SYM(plnh_, g_lnh);     uint32_t* plnh = (uint32_t*)plnh_;
    SYM(plnl_, g_lnl);     uint32_t* plnl = (uint32_t*)plnl_;
    SYM(pattnh_, g_attnh); uint32_t* pattnh = (uint32_t*)pattnh_;
    SYM(pattnl_, g_attnl); uint32_t* pattnl = (uint32_t*)pattnl_;
    SYM(phidh_, g_hidh);   uint32_t* phidh = (uint32_t*)phidh_;
    SYM(phidl_, g_hidl);   uint32_t* phidl = (uint32_t*)phidl_;
    #undef SYM

    // ---- weight conversion ----
    {
        long tq = (long)NLAY * 3 * HID * HID / 2;
        conv_pack_k<<<(unsigned)((tq + 255) / 256), 256>>>(wqkv, pwqkvh, pwqkvl, tq);
        long tw = (long)NLAY * HID * HID / 2;
        conv_pack_k<<<(unsigned)((tw + 255) / 256), 256>>>(wo, pwoh, pwol, tw);
        long tt = (long)VOC * HID / 2;
        conv_pack_h_k<<<(unsigned)((tt + 255) / 256), 256>>>(tok, ptokh, tt);
        conv_tr_k<<<dim3(HID / 64, FFD / 32, NLAY * NEXP), 256>>>(
            w1, pw1h, pw1l, HID, FFD, (long)HID * FFD, (long)FFD * (HID / 2));
        conv_tr_k<<<dim3(FFD / 64, HID / 32, NLAY * NEXP), 256>>>(
            w2, pw2h, pw2l, FFD, HID, (long)FFD * HID, (long)HID * (FFD / 2));
    }

    embed_k<<<SQ, 256>>>(idx, tok, pos);

    for (int l = 0; l < NLAY; l++) {
        ln_k<<<SQ, 256>>>(px, pln, plnh, plnl, ln1g + l * HID, ln1b + l * HID, 0);
        bfgemm_k<0><<<dim3(24, 16, 1), 256, SM_TOT>>>(
            plnh, plnl, HID / 2,
            pwqkvh + (long)l * 3 * HID * (HID / 2), pwqkvl + (long)l * 3 * HID * (HID / 2), 0,
            bqkv + (long)l * 3 * HID,
            pqkv, 3 * HID, nullptr, nullptr, 0,
            SQ, 3 * HID, HID, 0, 0, 0, nullptr, nullptr);
        attn_k<<<dim3(SQ / 64, NHEAD), 256>>>();
        bfgemm_k<0><<<dim3(8, 16, 1), 256, SM_TOT>>>(
            pattnh, pattnl, HID / 2,
            pwoh + (long)l * HID * (HID / 2), pwol + (long)l * HID * (HID / 2), 0,
            bo + (long)l * HID,
            px, HID, nullptr, nullptr, 0,
            SQ, HID, HID, 1, 0, 0, nullptr, nullptr);
        ln_k<<<SQ, 256>>>(px, pln, plnh, plnl, ln2g + l * HID, ln2b + l * HID, 0);
        zero_cnt_k<<<1, 32>>>();
        router_k<<<SQ, 128>>>(rw + (long)l * NEXP * HID);
        bfgemm_k<0><<<dim3(FFD / 128, 16, NEXP), 256, SM_TOT>>>(
            plnh, plnl, HID / 2,
            pw1h + (long)l * NEXP * FFD * (HID / 2), pw1l + (long)l * NEXP * FFD * (HID / 2),
            (long)FFD * (HID / 2),
            nullptr,
            nullptr, 0, phidh, phidl, FFD / 2,
            SQ, FFD, HID, 0, 1, 1, pel, pec);
        bfgemm_k<0><<<dim3(HID / 128, 16, NEXP), 256, SM_TOT>>>(
            phidh, phidl, FFD / 2,
            pw2h + (long)l * NEXP * HID * (FFD / 2), pw2l + (long)l * NEXP * HID * (FFD / 2),
            (long)HID * (FFD / 2),
            nullptr,
            pout2, HID, nullptr, nullptr, 0,
            SQ, HID, FFD, 0, 0, 2, pel, pec);
        combine_k<<<SQ, 256>>>();
    }

    // final LN emits fp16 split planes; lm_head is 1-term fp16
    ln_k<<<SQ, 256>>>(px, pln, plnh, plnl, lnfg, lnfb, 1);
    bfgemm_k<1><<<dim3(VOC / 128, 16, 1), 256, SM_TOT>>>(
        plnh, plnl, HID / 2,
        ptokh, ptokh, 0,
        nullptr,
        out, VOC, nullptr, nullptr, 0,
        SQ, VOC, HID, 0, 0, 0, nullptr, nullptr);
}

// round 16
// speedup vs baseline: 1.6573x; 1.6573x over previous
#include <cuda_runtime.h>
#include <cuda_bf16.h>
#include <cuda_fp16.h>
#include <math.h>
#include <stdint.h>

// ---- model dims ----
#define SQ   2048
#define HID  1024
#define NHEAD 16
#define HD   64
#define FFD  4096
#define NEXP 8
#define TOPK 2
#define VOC  32000
#define NLAY 2

typedef unsigned long long u64;

// ---------------- f32x2 helpers ----------------
__device__ __forceinline__ u64 pk2(float lo, float hi) {
    u64 r; asm("mov.b64 %0, {%1,%2};" : "=l"(r) : "f"(lo), "f"(hi)); return r;
}
__device__ __forceinline__ void upk2(u64 v, float& lo, float& hi) {
    asm("mov.b64 {%0,%1}, %2;" : "=f"(lo), "=f"(hi) : "l"(v));
}
__device__ __forceinline__ u64 ffma2(u64 a, u64 b, u64 c) {
    u64 d; asm("fma.rn.f32x2 %0, %1, %2, %3;" : "=l"(d) : "l"(a), "l"(b), "l"(c)); return d;
}
__device__ __forceinline__ u64 fmul2(u64 a, u64 b) {
    u64 d; asm("mul.rn.f32x2 %0, %1, %2;" : "=l"(d) : "l"(a), "l"(b)); return d;
}

// ---------------- bf16 / fp16 splits ----------------
__device__ __forceinline__ void bfsplit2(float x0, float x1, uint32_t& h, uint32_t& l) {
    __nv_bfloat16 h0 = __float2bfloat16(x0);
    __nv_bfloat16 h1 = __float2bfloat16(x1);
    float r0 = x0 - __bfloat162float(h0);
    float r1 = x1 - __bfloat162float(h1);
    __nv_bfloat16 l0 = __float2bfloat16(r0);
    __nv_bfloat16 l1 = __float2bfloat16(r1);
    h = ((uint32_t)__bfloat16_as_ushort(h1) << 16) | (uint32_t)__bfloat16_as_ushort(h0);
    l = ((uint32_t)__bfloat16_as_ushort(l1) << 16) | (uint32_t)__bfloat16_as_ushort(l0);
}
__device__ __forceinline__ void hsplit2(float x0, float x1, uint32_t& h, uint32_t& l) {
    __half h0 = __float2half_rn(x0);
    __half h1 = __float2half_rn(x1);
    float r0 = x0 - __half2float(h0);
    float r1 = x1 - __half2float(h1);
    __half l0 = __float2half_rn(r0);
    __half l1 = __float2half_rn(r1);
    h = ((uint32_t)__half_as_ushort(h1) << 16) | (uint32_t)__half_as_ushort(h0);
    l = ((uint32_t)__half_as_ushort(l1) << 16) | (uint32_t)__half_as_ushort(l0);
}
__device__ __forceinline__ void mma_bf16(float& d0, float& d1, float& d2, float& d3,
                                         uint32_t a0, uint32_t a1, uint32_t a2, uint32_t a3,
                                         uint32_t b0, uint32_t b1) {
    asm volatile(
        "mma.sync.aligned.m16n8k16.row.col.f32.bf16.bf16.f32 "
        "{%0,%1,%2,%3},{%4,%5,%6,%7},{%8,%9},{%0,%1,%2,%3};"
        : "+f"(d0), "+f"(d1), "+f"(d2), "+f"(d3)
        : "r"(a0), "r"(a1), "r"(a2), "r"(a3), "r"(b0), "r"(b1));
}
__device__ __forceinline__ void mma_f16(float& d0, float& d1, float& d2, float& d3,
                                        uint32_t a0, uint32_t a1, uint32_t a2, uint32_t a3,
                                        uint32_t b0, uint32_t b1) {
    asm volatile(
        "mma.sync.aligned.m16n8k16.row.col.f32.f16.f16.f32 "
        "{%0,%1,%2,%3},{%4,%5,%6,%7},{%8,%9},{%0,%1,%2,%3};"
        : "+f"(d0), "+f"(d1), "+f"(d2), "+f"(d3)
        : "r"(a0), "r"(a1), "r"(a2), "r"(a3), "r"(b0), "r"(b1));
}

// ---------------- cp.async ----------------
__device__ __forceinline__ uint32_t s2u(const void* p) {
    uint32_t a;
    asm("{ .reg .u64 t; cvta.to.shared.u64 t, %1; cvt.u32.u64 %0, t; }" : "=r"(a) : "l"(p));
    return a;
}
__device__ __forceinline__ void cpa16(uint32_t dst, const void* src) {
    asm volatile("cp.async.cg.shared.global [%0], [%1], 16;" :: "r"(dst), "l"(src));
}
#define CP_COMMIT() asm volatile("cp.async.commit_group;" ::: "memory")
#define CP_WAIT(n)  asm volatile("cp.async.wait_group %0;" :: "n"(n) : "memory")

// ---- scratch (device globals) ----
__device__ float g_x   [SQ * HID];
__device__ float g_ln  [SQ * HID];
__device__ float g_qkv [SQ * 3 * HID];
__device__ float g_out2[SQ * TOPK * HID];
__device__ float g_slotw[SQ * TOPK];
__device__ int   g_elist[NEXP * SQ];
__device__ int   g_ecnt [NEXP];

// pre-split 16-bit-pair planes (hi/lo), all K-major [rows][K/2] u32
__device__ uint32_t g_wqkvh[NLAY * 3 * HID * HID / 2], g_wqkvl[NLAY * 3 * HID * HID / 2];
__device__ uint32_t g_woh  [NLAY * HID * HID / 2],     g_wol  [NLAY * HID * HID / 2];
__device__ uint32_t g_w1h  [NLAY * NEXP * FFD * HID / 2], g_w1l[NLAY * NEXP * FFD * HID / 2];
__device__ uint32_t g_w2h  [NLAY * NEXP * HID * FFD / 2], g_w2l[NLAY * NEXP * HID * FFD / 2];
__device__ uint32_t g_tokh [VOC * HID / 2];              // fp16 (lm_head B, single plane)
__device__ uint32_t g_lnh  [SQ * HID / 2],             g_lnl  [SQ * HID / 2];
__device__ uint32_t g_attnh[SQ * HID / 2],             g_attnl[SQ * HID / 2];
__device__ uint32_t g_hidh [SQ * TOPK * FFD / 2],      g_hidl [SQ * TOPK * FFD / 2];

// ---------------------------------------------------------------------------
__global__ void embed_k(const int* __restrict__ idx,
                        const float* __restrict__ tok,
                        const float* __restrict__ pos) {
    int s = blockIdx.x;
    int row = idx[s];
    for (int h = threadIdx.x; h < HID; h += blockDim.x)
        g_x[s * HID + h] = tok[(long)row * HID + h] + pos[(long)s * HID + h];
}

// ---------------------------------------------------------------------------
__global__ void conv_pack_k(const float* __restrict__ src,
                            uint32_t* __restrict__ dh, uint32_t* __restrict__ dl,
                            long total) {
    long i = (long)blockIdx.x * 256 + threadIdx.x;
    if (i >= total) return;
    float2 v = ((const float2*)src)[i];
    uint32_t h, l;
    bfsplit2(v.x, v.y, h, l);
    dh[i] = h; dl[i] = l;
}

// fp16 single-plane pack (lm_head B)
__global__ void conv_pack_h_k(const float* __restrict__ src,
                              uint32_t* __restrict__ dh, long total) {
    long i = (long)blockIdx.x * 256 + threadIdx.x;
    if (i >= total) return;
    float2 v = ((const float2*)src)[i];
    __half h0 = __float2half_rn(v.x), h1 = __float2half_rn(v.y);
    dh[i] = ((uint32_t)__half_as_ushort(h1) << 16) | (uint32_t)__half_as_ushort(h0);
}

// transpose+pack: src f32 [Kd,Nd] per matrix -> bf16 planes [Nd,Kd/2]
__global__ void conv_tr_k(const float* __restrict__ src,
                          uint32_t* __restrict__ dh, uint32_t* __restrict__ dl,
                          int Kd, int Nd, long msi, long mso) {
    __shared__ float sm[64][33];
    int z = blockIdx.z;
    int k0 = blockIdx.x * 64, n0 = blockIdx.y * 32;
    int t = threadIdx.x;
    const float* S = src + (long)z * msi;
    int tk = t >> 5, tn = t & 31;
    #pragma unroll
    for (int i = 0; i < 8; i++)
        sm[tk + 8 * i][tn] = S[(long)(k0 + tk + 8 * i) * Nd + n0 + tn];
    __syncthreads();
    int kk = t & 31, nl = t >> 5;
    #pragma unroll
    for (int j = 0; j < 4; j++) {
        int n = nl + 8 * j;
        uint32_t h, l;
        bfsplit2(sm[2 * kk][n], sm[2 * kk + 1][n], h, l);
        long o = (long)z * mso + (long)(n0 + n) * (Kd >> 1) + (k0 >> 1) + kk;
        dh[o] = h; dl[o] = l;
    }
}

// ---------------------------------------------------------------------------
// LayerNorm; fp16mode=1 emits fp16 split planes (for lm_head), else bf16.
__global__ void ln_k(const float* __restrict__ in, float* __restrict__ outf,
                     uint32_t* __restrict__ oh, uint32_t* __restrict__ ol,
                     const float* __restrict__ g, const float* __restrict__ b,
                     int fp16mode) {
    int s = blockIdx.x, t = threadIdx.x;
    __shared__ float red[256];
    float4 v = ((const float4*)(in + (long)s * HID))[t];
    red[t] = v.x + v.y + v.z + v.w;
    __syncthreads();
    for (int o = 128; o > 0; o >>= 1) { if (t < o) red[t] += red[t + o]; __syncthreads(); }
    float mu = red[0] * (1.0f / HID);
    __syncthreads();
    float dx = v.x - mu, dy = v.y - mu, dz = v.z - mu, dw = v.w - mu;
    red[t] = dx * dx + dy * dy + dz * dz + dw * dw;
    __syncthreads();
    for (int o = 128; o > 0; o >>= 1) { if (t < o) red[t] += red[t + o]; __syncthreads(); }
    float inv = rsqrtf(red[0] * (1.0f / HID) + 1e-5f);
    float4 gg = ((const float4*)g)[t], bb = ((const float4*)b)[t];
    float4 o4;
    o4.x = dx * inv * gg.x + bb.x;
    o4.y = dy * inv * gg.y + bb.y;
    o4.z = dz * inv * gg.z + bb.z;
    o4.w = dw * inv * gg.w + bb.w;
    ((float4*)(outf + (long)s * HID))[t] = o4;
    uint32_t h0, l0, h1, l1;
    if (fp16mode) {
        hsplit2(o4.x, o4.y, h0, l0);
        hsplit2(o4.z, o4.w, h1, l1);
    } else {
        bfsplit2(o4.x, o4.y, h0, l0);
        bfsplit2(o4.z, o4.w, h1, l1);
    }
    long p = (long)s * 512 + 2 * t;
    oh[p] = h0; oh[p + 1] = h1; ol[p] = l0; ol[p + 1] = l1;
}

// ---------------------------------------------------------------------------
// Tensor-core GEMM on pre-split planes, cp.async double-buffered.
// H2T=0: 3-term bf16 (hh+hl+lh). H2T=1: 1-term fp16 (ah·bh only; Al/Bl unused).
#define ASTRIDE 20
#define PLANE   (128 * ASTRIDE)
#define BUFU32  (4 * PLANE)
#define SM_TOT  (2 * BUFU32 * 4)   // 81920 B

template <int H2T>
__global__ void __launch_bounds__(256, 2) bfgemm_k(
        const uint32_t* __restrict__ Ah, const uint32_t* __restrict__ Al, int lda2,
        const uint32_t* __restrict__ Bh_, const uint32_t* __restrict__ Bl_, long strideB,
        const float* __restrict__ bias,
        float* __restrict__ C, int ldc,
        uint32_t* __restrict__ Chi, uint32_t* __restrict__ Clo, int ldc2,
        int M, int N, int K,
        int accum, int gelu, int row_mode,
        const int* __restrict__ elist, const int* __restrict__ ecnt) {
    extern __shared__ uint32_t smem[];
    uint32_t sb = s2u(smem);

    int e = blockIdx.z;
    long eoff = (long)e * strideB;
    int Me = M;
    const int* list = nullptr;
    if (row_mode) { Me = ecnt[e]; list = elist + e * SQ; }
    int m0 = blockIdx.y * 128;
    if (m0 >= Me) return;
    int n0 = blockIdx.x * 128;

    int t = threadIdx.x;
    int lane = t & 31, wid = t >> 5;
    int warp_m = wid >> 2, warp_n = wid & 3;
    int g = lane >> 2, t4 = lane & 3;

    int am = t & 127, seg = t >> 7;
    int lrow = m0 + am;
    const uint32_t* Arh = nullptr;
    const uint32_t* Arl = nullptr;
    if (lrow < Me) {
        long gr;
        if (row_mode == 0) gr = lrow;
        else { int slot = list[lrow]; gr = (row_mode == 1) ? (slot >> 1) : slot; }
        Arh = Ah + gr * (long)lda2;
        Arl = Al + gr * (long)lda2;
    }
    int ldb2 = K >> 1;
    const uint32_t* Brh = Bh_ + eoff + (long)(n0 + am) * ldb2;
    const uint32_t* Brl = H2T ? nullptr : (Bl_ + eoff + (long)(n0 + am) * ldb2);

    int nch = K / 32;

    auto issue = [&](int c, int b) {
        int off = c * 16 + seg * 8;
        uint32_t base = sb + (uint32_t)(b * BUFU32) * 4u;
        uint32_t da = base + (uint32_t)(am * ASTRIDE + seg * 8) * 4u;
        if (Arh) {
            cpa16(da,                    Arh + off);
            cpa16(da + 16,               Arh + off + 4);
            if (!H2T) {
                cpa16(da + PLANE * 4,        Arl + off);
                cpa16(da + PLANE * 4 + 16,   Arl + off + 4);
            }
        }
        uint32_t db = base + (uint32_t)(2 * PLANE + am * ASTRIDE + seg * 8) * 4u;
        cpa16(db,                    Brh + off);
        cpa16(db + 16,               Brh + off + 4);
        if (!H2T) {
            cpa16(db + PLANE * 4,        Brl + off);
            cpa16(db + PLANE * 4 + 16,   Brl + off + 4);
        }
        CP_COMMIT();
    };

    float acc[4][4][4];
    #pragma unroll
    for (int i = 0; i < 4; i++)
        #pragma unroll
        for (int j = 0; j < 4; j++)
            #pragma unroll
            for (int c = 0; c < 4; c++) acc[i][j][c] = 0.f;

    issue(0, 0);
    for (int c = 0; c < nch; c++) {
        int b = c & 1;
        if (c + 1 < nch) { issue(c + 1, b ^ 1); CP_WAIT(1); }
        else             { CP_WAIT(0); }
        __syncthreads();

        const uint32_t* base = smem + b * BUFU32;
        const uint32_t* pah = base + (warp_m * 64) * ASTRIDE;
        const uint32_t* pal = base + PLANE + (warp_m * 64) * ASTRIDE;
        const uint32_t* pbh = base + 2 * PLANE + (warp_n * 32) * ASTRIDE;
        const uint32_t* pbl = base + 3 * PLANE + (warp_n * 32) * ASTRIDE;

        #pragma unroll
        for (int ks = 0; ks < 2; ks++) {
            int kc = ks * 8;
            uint32_t afh[4][4], afl[4][4], bfh[4][2], bfl[4][2];
            #pragma unroll
            for (int mt = 0; mt < 4; mt++) {
                int r0 = (mt * 16 + g) * ASTRIDE + kc + t4;
                int r1 = (mt * 16 + g + 8) * ASTRIDE + kc + t4;
                afh[mt][0] = pah[r0]; afh[mt][1] = pah[r1];
                afh[mt][2] = pah[r0 + 4]; afh[mt][3] = pah[r1 + 4];
                if (!H2T) {
                    afl[mt][0] = pal[r0]; afl[mt][1] = pal[r1];
                    afl[mt][2] = pal[r0 + 4]; afl[mt][3] = pal[r1 + 4];
                }
            }
            #pragma unroll
            for (int nt = 0; nt < 4; nt++) {
                int r = (nt * 8 + g) * ASTRIDE + kc + t4;
                bfh[nt][0] = pbh[r]; bfh[nt][1] = pbh[r + 4];
                if (!H2T) { bfl[nt][0] = pbl[r]; bfl[nt][1] = pbl[r + 4]; }
            }
            #pragma unroll
            for (int mt = 0; mt < 4; mt++)
                #pragma unroll
                for (int nt = 0; nt < 4; nt++) {
                    float* a = acc[mt][nt];
                    if (H2T) {
                        mma_f16(a[0], a[1], a[2], a[3],
                                afh[mt][0], afh[mt][1], afh[mt][2], afh[mt][3],
                                bfh[nt][0], bfh[nt][1]);
                    } else {
                        mma_bf16(a[0], a[1], a[2], a[3],
                                 afh[mt][0], afh[mt][1], afh[mt][2], afh[mt][3],
                                 bfh[nt][0], bfh[nt][1]);
                        mma_bf16(a[0], a[1], a[2], a[3],
                                 afh[mt][0], afh[mt][1], afh[mt][2], afh[mt][3],
                                 bfl[nt][0], bfl[nt][1]);
                        mma_bf16(a[0], a[1], a[2], a[3],
                                 afl[mt][0], afl[mt][1], afl[mt][2], afl[mt][3],
                                 bfh[nt][0], bfh[nt][1]);
                    }
                }
        }
        __syncthreads();
    }

    // ---- epilogue ----
    #pragma unroll
    for (int mt = 0; mt < 4; mt++) {
        int rbase = warp_m * 64 + mt * 16 + g;
        #pragma unroll
        for (int p = 0; p < 2; p++) {
            int lr = m0 + rbase + 8 * p;
            if (lr >= Me) continue;
            long crow = row_mode ? (long)list[lr] : (long)lr;
            if (Chi) {
                long ob = crow * (long)ldc2 + ((n0 + warp_n * 32) >> 1);
                #pragma unroll
                for (int nt = 0; nt < 4; nt++) {
                    int col = nt * 8 + 2 * t4;
                    float v0 = acc[mt][nt][2 * p];
                    float v1 = acc[mt][nt][2 * p + 1];
                    if (gelu) { v0 = v0 * normcdff(v0); v1 = v1 * normcdff(v1); }
                    uint32_t h, l;
                    bfsplit2(v0, v1, h, l);
                    Chi[ob + (col >> 1)] = h;
                    Clo[ob + (col >> 1)] = l;
                }
            } else {
                float* cp = C + crow * (long)ldc + n0 + warp_n * 32;
                const float* bp = bias ? bias + n0 + warp_n * 32 : nullptr;
                #pragma unroll
                for (int nt = 0; nt < 4; nt++) {
                    int col = nt * 8 + 2 * t4;
                    float v0 = acc[mt][nt][2 * p];
                    float v1 = acc[mt][nt][2 * p + 1];
                    if (bp) { v0 += bp[col]; v1 += bp[col + 1]; }
                    if (gelu) { v0 = v0 * normcdff(v0); v1 = v1 * normcdff(v1); }
                    if (accum) { v0 += cp[col]; v1 += cp[col + 1]; }
                    *(float2*)&cp[col] = make_float2(v0, v1);
                }
            }
        }
    }
}

// ---------------------------------------------------------------------------
// Causal flash attention: 256 threads = 64 queries x 4 quarter-threads (16 dims),
// batch-8 online softmax, f32x2 math; writes split planes for the Wo GEMM.
__global__ void attn_k() {
    int h  = blockIdx.y;
    int q0 = blockIdx.x * 64;
    int t  = threadIdx.x;
    int ql = t >> 2, q4 = t & 3;
    int q  = q0 + ql;

    u64 qv2[8];
    {
        const float* qptr = &g_qkv[(long)q * 3072 + h * 64 + q4 * 16];
        #pragma unroll
        for (int i = 0; i < 4; i++) {
            ulonglong2 v = *(const ulonglong2*)&qptr[i * 4];
            qv2[2 * i] = v.x; qv2[2 * i + 1] = v.y;
        }
    }

    float m = -1e30f, l = 0.f;
    u64 acc2[8];
    #pragma unroll
    for (int i = 0; i < 8; i++) acc2[i] = 0ULL;

    __shared__ float Ks[64][64];
    __shared__ float Vs[64][64];

    for (int kt = 0; kt <= q0 + 63; kt += 64) {
        #pragma unroll
        for (int i = t * 4; i < 64 * 64; i += 256 * 4) {
            int kk = i >> 6, d = i & 63;
            *(float4*)&Ks[kk][d] = *(const float4*)&g_qkv[(long)(kt + kk) * 3072 + 1024 + h * 64 + d];
            *(float4*)&Vs[kk][d] = *(const float4*)&g_qkv[(long)(kt + kk) * 3072 + 2048 + h * 64 + d];
        }
        __syncthreads();

        int kmax = q - kt + 1;
        if (kmax > 64) kmax = 64;

        for (int kb = 0; kb < 64; kb += 8) {
            float s[8];
            #pragma unroll
            for (int j = 0; j < 8; j++) {
                const u64* K2 = (const u64*)&Ks[kb + j][q4 * 16];
                u64 p2 = 0ULL;
                #pragma unroll
                for (int i = 0; i < 8; i++) p2 = ffma2(qv2[i], K2[i], p2);
                float lo, hi;
                upk2(p2, lo, hi);
                float p = lo + hi;
                p += __shfl_xor_sync(0xffffffffu, p, 1);
                p += __shfl_xor_sync(0xffffffffu, p, 2);
                s[j] = p * 0.125f;
            }

            int c = kmax - kb; if (c > 8) c = 8;
            if (c <= 0) continue;

            float bm = s[0];
            #pragma unroll
            for (int j = 1; j < 8; j++) if (j < c) bm = fmaxf(bm, s[j]);
            float mn = fmaxf(m, bm);
            float cor = __expf(m - mn);
            m = mn;
            l *= cor;
            u64 cor2 = pk2(cor, cor);
            #pragma unroll
            for (int i = 0; i < 8; i++) acc2[i] = fmul2(acc2[i], cor2);

            #pragma unroll
            for (int j = 0; j < 8; j++) {
                if (j >= c) break;
                float pe = __expf(s[j] - mn);
                l += pe;
                u64 pe2 = pk2(pe, pe);
                const u64* V2 = (const u64*)&Vs[kb + j][q4 * 16];
                #pragma unroll
                for (int i = 0; i < 8; i++) acc2[i] = ffma2(V2[i], pe2, acc2[i]);
            }
        }
        __syncthreads();
    }

    float inv = 1.f / l;
    long pidx = (long)q * 512 + h * 32 + q4 * 8;
    #pragma unroll
    for (int i = 0; i < 8; i++) {
        float lo, hi;
        upk2(acc2[i], lo, hi);
        uint32_t hh, ll;
        bfsplit2(lo * inv, hi * inv, hh, ll);
        g_attnh[pidx + i] = hh;
        g_attnl[pidx + i] = ll;
    }
}

// ---------------------------------------------------------------------------
__global__ void zero_cnt_k() { if (threadIdx.x < NEXP) g_ecnt[threadIdx.x] = 0; }

__global__ void router_k(const float* __restrict__ rw) {
    int tok = blockIdx.x, t = threadIdx.x;   // 128 threads
    __shared__ float sm[NEXP][128];
    __shared__ float logits[NEXP];
    const float* xr = g_ln + (long)tok * HID;

    for (int e = 0; e < NEXP; e++) {
        float s = 0.f;
        for (int j = t; j < HID; j += 128) s += xr[j] * rw[e * HID + j];
        sm[e][t] = s;
    }
    __syncthreads();
    if (t < NEXP) {
        float s = 0.f;
        for (int j = 0; j < 128; j++) s += sm[t][j];
        logits[t] = s;
    }
    __syncthreads();
    if (t == 0) {
        float mx = logits[0];
        for (int e = 1; e < NEXP; e++) mx = fmaxf(mx, logits[e]);
        float p[NEXP], den = 0.f;
        for (int e = 0; e < NEXP; e++) { p[e] = expf(logits[e] - mx); den += p[e]; }
        float idn = 1.f / den;
        for (int e = 0; e < NEXP; e++) p[e] *= idn;
        int i1 = 0;
        for (int e = 1; e < NEXP; e++) if (p[e] > p[i1]) i1 = e;
        int i2 = -1;
        for (int e = 0; e < NEXP; e++) {
            if (e == i1) continue;
            if (i2 < 0 || p[e] > p[i2]) i2 = e;
        }
        g_slotw[tok * 2 + 0] = p[i1];
        g_slotw[tok * 2 + 1] = p[i2];
        int p1 = atomicAdd(&g_ecnt[i1], 1); g_elist[i1 * SQ + p1] = tok * 2 + 0;
        int p2 = atomicAdd(&g_ecnt[i2], 1); g_elist[i2 * SQ + p2] = tok * 2 + 1;
    }
}

// ---------------------------------------------------------------------------
__global__ void combine_k() {
    int tok = blockIdx.x;
    float w0 = g_slotw[tok * 2 + 0];
    float w1 = g_slotw[tok * 2 + 1];
    const float* o0 = g_out2 + (long)(tok * 2 + 0) * HID;
    const float* o1 = g_out2 + (long)(tok * 2 + 1) * HID;
    float* xr = g_x + (long)tok * HID;
    for (int h = threadIdx.x; h < HID; h += blockDim.x)
        xr[h] += w0 * o0[h] + w1 * o1[h];
}

// ---------------------------------------------------------------------------
extern "C" void kernel_launch(void* const* d_in, const int* in_sizes, int n_in,
                              void* d_out, int out_size) {
    const int*   idx  = (const int*)  d_in[0];
    const float* tok  = (const float*)d_in[1];
    const float* pos  = (const float*)d_in[2];
    const float* ln1g = (const float*)d_in[3];
    const float* ln1b = (const float*)d_in[4];
    const float* wqkv = (const float*)d_in[5];
    const float* bqkv = (const float*)d_in[6];
    const float* wo   = (const float*)d_in[7];
    const float* bo   = (const float*)d_in[8];
    const float* ln2g = (const float*)d_in[9];
    const float* ln2b = (const float*)d_in[10];
    const float* rw   = (const float*)d_in[11];
    const float* w1   = (const float*)d_in[12];
    const float* w2   = (const float*)d_in[13];
    const float* lnfg = (const float*)d_in[14];
    const float* lnfb = (const float*)d_in[15];
    float* out = (float*)d_out;

    cudaFuncSetAttribute(bfgemm_k<0>, cudaFuncAttributeMaxDynamicSharedMemorySize, SM_TOT);
    cudaFuncSetAttribute(bfgemm_k<1>, cudaFuncAttributeMaxDynamicSharedMemorySize, SM_TOT);

    void* p_;
    #define SYM(var, sym) cudaGetSymbolAddress(&p_, sym); auto var = p_
    SYM(px_, g_x);        float* px = (float*)px_;
    SYM(pln_, g_ln);      float* pln = (float*)pln_;
    SYM(pqkv_, g_qkv);    float* pqkv = (float*)pqkv_;
    SYM(pout2_, g_out2);  float* pout2 = (float*)pout2_;
    SYM(pel_, g_elist);   const int* pel = (const int*)pel_;
    SYM(pec_, g_ecnt);    const int* pec = (const int*)pec_;
    SYM(pwqkvh_, g_wqkvh); uint32_t* pwqkvh = (uint32_t*)pwqkvh_;
    SYM(pwqkvl_, g_wqkvl); uint32_t* pwqkvl = (uint32_t*)pwqkvl_;
    SYM(pwoh_, g_woh);     uint32_t* pwoh = (uint32_t*)pwoh_;
    SYM(pwol_, g_wol);     uint32_t* pwol = (uint32_t*)pwol_;
    SYM(pw1h_, g_w1h);     uint32_t* pw1h = (uint32_t*)pw1h_;
    SYM(pw1l_, g_w1l);     uint32_t* pw1l = (uint32_t*)pw1l_;
    SYM(pw2h_, g_w2h);     uint32_t* pw2h = (uint32_t*)pw2h_;
    SYM(pw2l_, g_w2l);     uint32_t* pw2l = (uint32_t*)pw2l_;
    SYM(ptokh_, g_tokh);   uint32_t* ptokh = (uint32_t*)ptokh_;
    SYM(plnh_, g_lnh);     uint32_t* plnh = (uint32_t*)plnh_;
    SYM(plnl_, g_lnl);     uint32_t* plnl = (uint32_t*)plnl_;
    SYM(pattnh_, g_attnh); uint32_t* pattnh = (uint32_t*)pattnh_;
    SYM(pattnl_, g_attnl); uint32_t* pattnl = (uint32_t*)pattnl_;
    SYM(phidh_, g_hidh);   uint32_t* phidh = (uint32_t*)phidh_;
    SYM(phidl_, g_hidl);   uint32_t* phidl = (uint32_t*)phidl_;
    #undef SYM

    // ---- weight conversion ----
    {
        long tq = (long)NLAY * 3 * HID * HID / 2;
        conv_pack_k<<<(unsigned)((tq + 255) / 256), 256>>>(wqkv, pwqkvh, pwqkvl, tq);
        long tw = (long)NLAY * HID * HID / 2;
        conv_pack_k<<<(unsigned)((tw + 255) / 256), 256>>>(wo, pwoh, pwol, tw);
        long tt = (long)VOC * HID / 2;
        conv_pack_h_k<<<(unsigned)((tt + 255) / 256), 256>>>(tok, ptokh, tt);
        conv_tr_k<<<dim3(HID / 64, FFD / 32, NLAY * NEXP), 256>>>(
            w1, pw1h, pw1l, HID, FFD, (long)HID * FFD, (long)FFD * (HID / 2));
        conv_tr_k<<<dim3(FFD / 64, HID / 32, NLAY * NEXP), 256>>>(
            w2, pw2h, pw2l, FFD, HID, (long)FFD * HID, (long)HID * (FFD / 2));
    }

    embed_k<<<SQ, 256>>>(idx, tok, pos);

    for (int l = 0; l < NLAY; l++) {
        ln_k<<<SQ, 256>>>(px, pln, plnh, plnl, ln1g + l * HID, ln1b + l * HID, 0);
        bfgemm_k<0><<<dim3(24, 16, 1), 256, SM_TOT>>>(
            plnh, plnl, HID / 2,
            pwqkvh + (long)l * 3 * HID * (HID / 2), pwqkvl + (long)l * 3 * HID * (HID / 2), 0,
            bqkv + (long)l * 3 * HID,
            pqkv, 3 * HID, nullptr, nullptr, 0,
            SQ, 3 * HID, HID, 0, 0, 0, nullptr, nullptr);
        attn_k<<<dim3(SQ / 64, NHEAD), 256>>>();
        bfgemm_k<0><<<dim3(8, 16, 1), 256, SM_TOT>>>(
            pattnh, pattnl, HID / 2,
            pwoh + (long)l * HID * (HID / 2), pwol + (long)l * HID * (HID / 2), 0,
            bo + (long)l * HID,
            px, HID, nullptr, nullptr, 0,
            SQ, HID, HID, 1, 0, 0, nullptr, nullptr);
        ln_k<<<SQ, 256>>>(px, pln, plnh, plnl, ln2g + l * HID, ln2b + l * HID, 0);
        zero_cnt_k<<<1, 32>>>();
        router_k<<<SQ, 128>>>(rw + (long)l * NEXP * HID);
        bfgemm_k<0><<<dim3(FFD / 128, 16, NEXP), 256, SM_TOT>>>(
            plnh, plnl, HID / 2,
            pw1h + (long)l * NEXP * FFD * (HID / 2), pw1l + (long)l * NEXP * FFD * (HID / 2),
            (long)FFD * (HID / 2),
            nullptr,
            nullptr, 0, phidh, phidl, FFD / 2,
            SQ, FFD, HID, 0, 1, 1, pel, pec);
        bfgemm_k<0><<<dim3(HID / 128, 16, NEXP), 256, SM_TOT>>>(
            phidh, phidl, FFD / 2,
            pw2h + (long)l * NEXP * HID * (FFD / 2), pw2l + (long)l * NEXP * HID * (FFD / 2),
            (long)HID * (FFD / 2),
            nullptr,
            pout2, HID, nullptr, nullptr, 0,
            SQ, HID, FFD, 0, 0, 2, pel, pec);
        combine_k<<<SQ, 256>>>();
    }

    // final LN emits fp16 split planes; lm_head is 1-term fp16
    ln_k<<<SQ, 256>>>(px, pln, plnh, plnl, lnfg, lnfb, 1);
    bfgemm_k<1><<<dim3(VOC / 128, 16, 1), 256, SM_TOT>>>(
        plnh, plnl, HID / 2,
        ptokh, ptokh, 0,
        nullptr,
        out, VOC, nullptr, nullptr, 0,
        SQ, VOC, HID, 0, 0, 0, nullptr, nullptr);
}

// round 17
// speedup vs baseline: 1.7835x; 1.0761x over previous
#include <cuda_runtime.h>
#include <cuda_bf16.h>
#include <cuda_fp16.h>
#include <math.h>
#include <stdint.h>

// ---- model dims ----
#define SQ   2048
#define HID  1024
#define NHEAD 16
#define HD   64
#define FFD  4096
#define NEXP 8
#define TOPK 2
#define VOC  32000
#define NLAY 2
#define NCH  4          // attention split-K chunks
#define CHK  512        // keys per chunk

typedef unsigned long long u64;

// ---------------- f32x2 helpers ----------------
__device__ __forceinline__ u64 pk2(float lo, float hi) {
    u64 r; asm("mov.b64 %0, {%1,%2};" : "=l"(r) : "f"(lo), "f"(hi)); return r;
}
__device__ __forceinline__ void upk2(u64 v, float& lo, float& hi) {
    asm("mov.b64 {%0,%1}, %2;" : "=f"(lo), "=f"(hi) : "l"(v));
}
__device__ __forceinline__ u64 ffma2(u64 a, u64 b, u64 c) {
    u64 d; asm("fma.rn.f32x2 %0, %1, %2, %3;" : "=l"(d) : "l"(a), "l"(b), "l"(c)); return d;
}
__device__ __forceinline__ u64 fmul2(u64 a, u64 b) {
    u64 d; asm("mul.rn.f32x2 %0, %1, %2;" : "=l"(d) : "l"(a), "l"(b)); return d;
}

// ---------------- bf16 / fp16 splits ----------------
__device__ __forceinline__ void bfsplit2(float x0, float x1, uint32_t& h, uint32_t& l) {
    __nv_bfloat16 h0 = __float2bfloat16(x0);
    __nv_bfloat16 h1 = __float2bfloat16(x1);
    float r0 = x0 - __bfloat162float(h0);
    float r1 = x1 - __bfloat162float(h1);
    __nv_bfloat16 l0 = __float2bfloat16(r0);
    __nv_bfloat16 l1 = __float2bfloat16(r1);
    h = ((uint32_t)__bfloat16_as_ushort(h1) << 16) | (uint32_t)__bfloat16_as_ushort(h0);
    l = ((uint32_t)__bfloat16_as_ushort(l1) << 16) | (uint32_t)__bfloat16_as_ushort(l0);
}
__device__ __forceinline__ void hsplit2(float x0, float x1, uint32_t& h, uint32_t& l) {
    __half h0 = __float2half_rn(x0);
    __half h1 = __float2half_rn(x1);
    float r0 = x0 - __half2float(h0);
    float r1 = x1 - __half2float(h1);
    __half l0 = __float2half_rn(r0);
    __half l1 = __float2half_rn(r1);
    h = ((uint32_t)__half_as_ushort(h1) << 16) | (uint32_t)__half_as_ushort(h0);
    l = ((uint32_t)__half_as_ushort(l1) << 16) | (uint32_t)__half_as_ushort(l0);
}
__device__ __forceinline__ void mma_bf16(float& d0, float& d1, float& d2, float& d3,
                                         uint32_t a0, uint32_t a1, uint32_t a2, uint32_t a3,
                                         uint32_t b0, uint32_t b1) {
    asm volatile(
        "mma.sync.aligned.m16n8k16.row.col.f32.bf16.bf16.f32 "
        "{%0,%1,%2,%3},{%4,%5,%6,%7},{%8,%9},{%0,%1,%2,%3};"
        : "+f"(d0), "+f"(d1), "+f"(d2), "+f"(d3)
        : "r"(a0), "r"(a1), "r"(a2), "r"(a3), "r"(b0), "r"(b1));
}
__device__ __forceinline__ void mma_f16(float& d0, float& d1, float& d2, float& d3,
                                        uint32_t a0, uint32_t a1, uint32_t a2, uint32_t a3,
                                        uint32_t b0, uint32_t b1) {
    asm volatile(
        "mma.sync.aligned.m16n8k16.row.col.f32.f16.f16.f32 "
        "{%0,%1,%2,%3},{%4,%5,%6,%7},{%8,%9},{%0,%1,%2,%3};"
        : "+f"(d0), "+f"(d1), "+f"(d2), "+f"(d3)
        : "r"(a0), "r"(a1), "r"(a2), "r"(a3), "r"(b0), "r"(b1));
}

// ---------------- cp.async ----------------
__device__ __forceinline__ uint32_t s2u(const void* p) {
    uint32_t a;
    asm("{ .reg .u64 t; cvta.to.shared.u64 t, %1; cvt.u32.u64 %0, t; }" : "=r"(a) : "l"(p));
    return a;
}
__device__ __forceinline__ void cpa16(uint32_t dst, const void* src) {
    asm volatile("cp.async.cg.shared.global [%0], [%1], 16;" :: "r"(dst), "l"(src));
}
#define CP_COMMIT() asm volatile("cp.async.commit_group;" ::: "memory")
#define CP_WAIT(n)  asm volatile("cp.async.wait_group %0;" :: "n"(n) : "memory")

// ---- scratch (device globals) ----
__device__ float g_x   [SQ * HID];
__device__ float g_ln  [SQ * HID];
__device__ float g_qkv [SQ * 3 * HID];
__device__ float g_out2[SQ * TOPK * HID];
__device__ float g_slotw[SQ * TOPK];
__device__ int   g_elist[NEXP * SQ];
__device__ int   g_ecnt [NEXP];

// attention split-K partials
__device__ float g_pm  [NCH * NHEAD * SQ];
__device__ float g_pl  [NCH * NHEAD * SQ];
__device__ float g_pacc[(long)NCH * NHEAD * SQ * HD];

// pre-split 16-bit-pair planes (hi/lo), all K-major [rows][K/2] u32
__device__ uint32_t g_wqkvh[NLAY * 3 * HID * HID / 2], g_wqkvl[NLAY * 3 * HID * HID / 2];
__device__ uint32_t g_woh  [NLAY * HID * HID / 2],     g_wol  [NLAY * HID * HID / 2];
__device__ uint32_t g_w1h  [NLAY * NEXP * FFD * HID / 2], g_w1l[NLAY * NEXP * FFD * HID / 2];
__device__ uint32_t g_w2h  [NLAY * NEXP * HID * FFD / 2], g_w2l[NLAY * NEXP * HID * FFD / 2];
__device__ uint32_t g_tokh [VOC * HID / 2];              // fp16 (lm_head B, single plane)
__device__ uint32_t g_lnh  [SQ * HID / 2],             g_lnl  [SQ * HID / 2];
__device__ uint32_t g_attnh[SQ * HID / 2],             g_attnl[SQ * HID / 2];
__device__ uint32_t g_hidh [SQ * TOPK * FFD / 2],      g_hidl [SQ * TOPK * FFD / 2];

// ---------------------------------------------------------------------------
__global__ void embed_k(const int* __restrict__ idx,
                        const float* __restrict__ tok,
                        const float* __restrict__ pos) {
    int s = blockIdx.x;
    int row = idx[s];
    for (int h = threadIdx.x; h < HID; h += blockDim.x)
        g_x[s * HID + h] = tok[(long)row * HID + h] + pos[(long)s * HID + h];
}

// ---------------------------------------------------------------------------
__global__ void conv_pack_k(const float* __restrict__ src,
                            uint32_t* __restrict__ dh, uint32_t* __restrict__ dl,
                            long total) {
    long i = (long)blockIdx.x * 256 + threadIdx.x;
    if (i >= total) return;
    float2 v = ((const float2*)src)[i];
    uint32_t h, l;
    bfsplit2(v.x, v.y, h, l);
    dh[i] = h; dl[i] = l;
}

// fp16 single-plane pack (lm_head B)
__global__ void conv_pack_h_k(const float* __restrict__ src,
                              uint32_t* __restrict__ dh, long total) {
    long i = (long)blockIdx.x * 256 + threadIdx.x;
    if (i >= total) return;
    float2 v = ((const float2*)src)[i];
    __half h0 = __float2half_rn(v.x), h1 = __float2half_rn(v.y);
    dh[i] = ((uint32_t)__half_as_ushort(h1) << 16) | (uint32_t)__half_as_ushort(h0);
}

// transpose+pack: src f32 [Kd,Nd] per matrix -> bf16 planes [Nd,Kd/2]
__global__ void conv_tr_k(const float* __restrict__ src,
                          uint32_t* __restrict__ dh, uint32_t* __restrict__ dl,
                          int Kd, int Nd, long msi, long mso) {
    __shared__ float sm[64][33];
    int z = blockIdx.z;
    int k0 = blockIdx.x * 64, n0 = blockIdx.y * 32;
    int t = threadIdx.x;
    const float* S = src + (long)z * msi;
    int tk = t >> 5, tn = t & 31;
    #pragma unroll
    for (int i = 0; i < 8; i++)
        sm[tk + 8 * i][tn] = S[(long)(k0 + tk + 8 * i) * Nd + n0 + tn];
    __syncthreads();
    int kk = t & 31, nl = t >> 5;
    #pragma unroll
    for (int j = 0; j < 4; j++) {
        int n = nl + 8 * j;
        uint32_t h, l;
        bfsplit2(sm[2 * kk][n], sm[2 * kk + 1][n], h, l);
        long o = (long)z * mso + (long)(n0 + n) * (Kd >> 1) + (k0 >> 1) + kk;
        dh[o] = h; dl[o] = l;
    }
}

// ---------------------------------------------------------------------------
// LayerNorm; fp16mode=1 emits fp16 split planes (for lm_head), else bf16.
__global__ void ln_k(const float* __restrict__ in, float* __restrict__ outf,
                     uint32_t* __restrict__ oh, uint32_t* __restrict__ ol,
                     const float* __restrict__ g, const float* __restrict__ b,
                     int fp16mode) {
    int s = blockIdx.x, t = threadIdx.x;
    __shared__ float red[256];
    float4 v = ((const float4*)(in + (long)s * HID))[t];
    red[t] = v.x + v.y + v.z + v.w;
    __syncthreads();
    for (int o = 128; o > 0; o >>= 1) { if (t < o) red[t] += red[t + o]; __syncthreads(); }
    float mu = red[0] * (1.0f / HID);
    __syncthreads();
    float dx = v.x - mu, dy = v.y - mu, dz = v.z - mu, dw = v.w - mu;
    red[t] = dx * dx + dy * dy + dz * dz + dw * dw;
    __syncthreads();
    for (int o = 128; o > 0; o >>= 1) { if (t < o) red[t] += red[t + o]; __syncthreads(); }
    float inv = rsqrtf(red[0] * (1.0f / HID) + 1e-5f);
    float4 gg = ((const float4*)g)[t], bb = ((const float4*)b)[t];
    float4 o4;
    o4.x = dx * inv * gg.x + bb.x;
    o4.y = dy * inv * gg.y + bb.y;
    o4.z = dz * inv * gg.z + bb.z;
    o4.w = dw * inv * gg.w + bb.w;
    ((float4*)(outf + (long)s * HID))[t] = o4;
    uint32_t h0, l0, h1, l1;
    if (fp16mode) {
        hsplit2(o4.x, o4.y, h0, l0);
        hsplit2(o4.z, o4.w, h1, l1);
    } else {
        bfsplit2(o4.x, o4.y, h0, l0);
        bfsplit2(o4.z, o4.w, h1, l1);
    }
    long p = (long)s * 512 + 2 * t;
    oh[p] = h0; oh[p + 1] = h1; ol[p] = l0; ol[p + 1] = l1;
}

// ---------------------------------------------------------------------------
// Tensor-core GEMM on pre-split planes, cp.async double-buffered.
// H2T=0: 3-term bf16 (hh+hl+lh). H2T=1: 1-term fp16 (ah·bh only; Al/Bl unused).
#define ASTRIDE 20
#define PLANE   (128 * ASTRIDE)
#define BUFU32  (4 * PLANE)
#define SM_TOT  (2 * BUFU32 * 4)   // 81920 B

template <int H2T>
__global__ void __launch_bounds__(256, 2) bfgemm_k(
        const uint32_t* __restrict__ Ah, const uint32_t* __restrict__ Al, int lda2,
        const uint32_t* __restrict__ Bh_, const uint32_t* __restrict__ Bl_, long strideB,
        const float* __restrict__ bias,
        float* __restrict__ C, int ldc,
        uint32_t* __restrict__ Chi, uint32_t* __restrict__ Clo, int ldc2,
        int M, int N, int K,
        int accum, int gelu, int row_mode,
        const int* __restrict__ elist, const int* __restrict__ ecnt) {
    extern __shared__ uint32_t smem[];
    uint32_t sb = s2u(smem);

    int e = blockIdx.z;
    long eoff = (long)e * strideB;
    int Me = M;
    const int* list = nullptr;
    if (row_mode) { Me = ecnt[e]; list = elist + e * SQ; }
    int m0 = blockIdx.y * 128;
    if (m0 >= Me) return;
    int n0 = blockIdx.x * 128;

    int t = threadIdx.x;
    int lane = t & 31, wid = t >> 5;
    int warp_m = wid >> 2, warp_n = wid & 3;
    int g = lane >> 2, t4 = lane & 3;

    int am = t & 127, seg = t >> 7;
    int lrow = m0 + am;
    const uint32_t* Arh = nullptr;
    const uint32_t* Arl = nullptr;
    if (lrow < Me) {
        long gr;
        if (row_mode == 0) gr = lrow;
        else { int slot = list[lrow]; gr = (row_mode == 1) ? (slot >> 1) : slot; }
        Arh = Ah + gr * (long)lda2;
        Arl = Al + gr * (long)lda2;
    }
    int ldb2 = K >> 1;
    const uint32_t* Brh = Bh_ + eoff + (long)(n0 + am) * ldb2;
    const uint32_t* Brl = H2T ? nullptr : (Bl_ + eoff + (long)(n0 + am) * ldb2);

    int nch = K / 32;

    auto issue = [&](int c, int b) {
        int off = c * 16 + seg * 8;
        uint32_t base = sb + (uint32_t)(b * BUFU32) * 4u;
        uint32_t da = base + (uint32_t)(am * ASTRIDE + seg * 8) * 4u;
        if (Arh) {
            cpa16(da,                    Arh + off);
            cpa16(da + 16,               Arh + off + 4);
            if (!H2T) {
                cpa16(da + PLANE * 4,        Arl + off);
                cpa16(da + PLANE * 4 + 16,   Arl + off + 4);
            }
        }
        uint32_t db = base + (uint32_t)(2 * PLANE + am * ASTRIDE + seg * 8) * 4u;
        cpa16(db,                    Brh + off);
        cpa16(db + 16,               Brh + off + 4);
        if (!H2T) {
            cpa16(db + PLANE * 4,        Brl + off);
            cpa16(db + PLANE * 4 + 16,   Brl + off + 4);
        }
        CP_COMMIT();
    };

    float acc[4][4][4];
    #pragma unroll
    for (int i = 0; i < 4; i++)
        #pragma unroll
        for (int j = 0; j < 4; j++)
            #pragma unroll
            for (int c = 0; c < 4; c++) acc[i][j][c] = 0.f;

    issue(0, 0);
    for (int c = 0; c < nch; c++) {
        int b = c & 1;
        if (c + 1 < nch) { issue(c + 1, b ^ 1); CP_WAIT(1); }
        else             { CP_WAIT(0); }
        __syncthreads();

        const uint32_t* base = smem + b * BUFU32;
        const uint32_t* pah = base + (warp_m * 64) * ASTRIDE;
        const uint32_t* pal = base + PLANE + (warp_m * 64) * ASTRIDE;
        const uint32_t* pbh = base + 2 * PLANE + (warp_n * 32) * ASTRIDE;
        const uint32_t* pbl = base + 3 * PLANE + (warp_n * 32) * ASTRIDE;

        #pragma unroll
        for (int ks = 0; ks < 2; ks++) {
            int kc = ks * 8;
            uint32_t afh[4][4], afl[4][4], bfh[4][2], bfl[4][2];
            #pragma unroll
            for (int mt = 0; mt < 4; mt++) {
                int r0 = (mt * 16 + g) * ASTRIDE + kc + t4;
                int r1 = (mt * 16 + g + 8) * ASTRIDE + kc + t4;
                afh[mt][0] = pah[r0]; afh[mt][1] = pah[r1];
                afh[mt][2] = pah[r0 + 4]; afh[mt][3] = pah[r1 + 4];
                if (!H2T) {
                    afl[mt][0] = pal[r0]; afl[mt][1] = pal[r1];
                    afl[mt][2] = pal[r0 + 4]; afl[mt][3] = pal[r1 + 4];
                }
            }
            #pragma unroll
            for (int nt = 0; nt < 4; nt++) {
                int r = (nt * 8 + g) * ASTRIDE + kc + t4;
                bfh[nt][0] = pbh[r]; bfh[nt][1] = pbh[r + 4];
                if (!H2T) { bfl[nt][0] = pbl[r]; bfl[nt][1] = pbl[r + 4]; }
            }
            #pragma unroll
            for (int mt = 0; mt < 4; mt++)
                #pragma unroll
                for (int nt = 0; nt < 4; nt++) {
                    float* a = acc[mt][nt];
                    if (H2T) {
                        mma_f16(a[0], a[1], a[2], a[3],
                                afh[mt][0], afh[mt][1], afh[mt][2], afh[mt][3],
                                bfh[nt][0], bfh[nt][1]);
                    } else {
                        mma_bf16(a[0], a[1], a[2], a[3],
                                 afh[mt][0], afh[mt][1], afh[mt][2], afh[mt][3],
                                 bfh[nt][0], bfh[nt][1]);
                        mma_bf16(a[0], a[1], a[2], a[3],
                                 afh[mt][0], afh[mt][1], afh[mt][2], afh[mt][3],
                                 bfl[nt][0], bfl[nt][1]);
                        mma_bf16(a[0], a[1], a[2], a[3],
                                 afl[mt][0], afl[mt][1], afl[mt][2], afl[mt][3],
                                 bfh[nt][0], bfh[nt][1]);
                    }
                }
        }
        __syncthreads();
    }

    // ---- epilogue ----
    #pragma unroll
    for (int mt = 0; mt < 4; mt++) {
        int rbase = warp_m * 64 + mt * 16 + g;
        #pragma unroll
        for (int p = 0; p < 2; p++) {
            int lr = m0 + rbase + 8 * p;
            if (lr >= Me) continue;
            long crow = row_mode ? (long)list[lr] : (long)lr;
            if (Chi) {
                long ob = crow * (long)ldc2 + ((n0 + warp_n * 32) >> 1);
                #pragma unroll
                for (int nt = 0; nt < 4; nt++) {
                    int col = nt * 8 + 2 * t4;
                    float v0 = acc[mt][nt][2 * p];
                    float v1 = acc[mt][nt][2 * p + 1];
                    if (gelu) { v0 = v0 * normcdff(v0); v1 = v1 * normcdff(v1); }
                    uint32_t h, l;
                    bfsplit2(v0, v1, h, l);
                    Chi[ob + (col >> 1)] = h;
                    Clo[ob + (col >> 1)] = l;
                }
            } else {
                float* cp = C + crow * (long)ldc + n0 + warp_n * 32;
                const float* bp = bias ? bias + n0 + warp_n * 32 : nullptr;
                #pragma unroll
                for (int nt = 0; nt < 4; nt++) {
                    int col = nt * 8 + 2 * t4;
                    float v0 = acc[mt][nt][2 * p];
                    float v1 = acc[mt][nt][2 * p + 1];
                    if (bp) { v0 += bp[col]; v1 += bp[col + 1]; }
                    if (gelu) { v0 = v0 * normcdff(v0); v1 = v1 * normcdff(v1); }
                    if (accum) { v0 += cp[col]; v1 += cp[col + 1]; }
                    *(float2*)&cp[col] = make_float2(v0, v1);
                }
            }
        }
    }
}

// ---------------------------------------------------------------------------
// Split-K causal flash attention, stage 1 (partials per key-chunk).
// Block = (q-block of 64, head, chunk). 256 threads = 64 q x 4 quarter-threads.
// Chunk c covers keys [c*CHK, c*CHK+CHK) ∩ [0, q]. Blocks with no work exit.
__global__ void attn_part_k() {
    int qb = blockIdx.x, h = blockIdx.y, c = blockIdx.z;
    if (qb * 64 + 63 < c * CHK) return;   // entire q-block below chunk start
    int q0 = qb * 64;
    int t  = threadIdx.x;
    int ql = t >> 2, q4 = t & 3;
    int q  = q0 + ql;

    u64 qv2[8];
    {
        const float* qptr = &g_qkv[(long)q * 3072 + h * 64 + q4 * 16];
        #pragma unroll
        for (int i = 0; i < 4; i++) {
            ulonglong2 v = *(const ulonglong2*)&qptr[i * 4];
            qv2[2 * i] = v.x; qv2[2 * i + 1] = v.y;
        }
    }

    float m = -1e30f, l = 0.f;
    u64 acc2[8];
    #pragma unroll
    for (int i = 0; i < 8; i++) acc2[i] = 0ULL;

    __shared__ float Ks[64][64];
    __shared__ float Vs[64][64];

    int kbeg = c * CHK;
    int kend = kbeg + CHK;
    if (kend > q0 + 64) kend = q0 + 64;

    for (int kt = kbeg; kt < kend; kt += 64) {
        #pragma unroll
        for (int i = t * 4; i < 64 * 64; i += 256 * 4) {
            int kk = i >> 6, d = i & 63;
            *(float4*)&Ks[kk][d] = *(const float4*)&g_qkv[(long)(kt + kk) * 3072 + 1024 + h * 64 + d];
            *(float4*)&Vs[kk][d] = *(const float4*)&g_qkv[(long)(kt + kk) * 3072 + 2048 + h * 64 + d];
        }
        __syncthreads();

        int kmax = q - kt + 1;
        if (kmax > 64) kmax = 64;

        for (int kb = 0; kb < 64; kb += 8) {
            float s[8];
            #pragma unroll
            for (int j = 0; j < 8; j++) {
                const u64* K2 = (const u64*)&Ks[kb + j][q4 * 16];
                u64 p2 = 0ULL;
                #pragma unroll
                for (int i = 0; i < 8; i++) p2 = ffma2(qv2[i], K2[i], p2);
                float lo, hi;
                upk2(p2, lo, hi);
                float p = lo + hi;
                p += __shfl_xor_sync(0xffffffffu, p, 1);
                p += __shfl_xor_sync(0xffffffffu, p, 2);
                s[j] = p * 0.125f;
            }

            int cc = kmax - kb; if (cc > 8) cc = 8;
            if (cc <= 0) continue;

            float bm = s[0];
            #pragma unroll
            for (int j = 1; j < 8; j++) if (j < cc) bm = fmaxf(bm, s[j]);
            float mn = fmaxf(m, bm);
            float cor = __expf(m - mn);
            m = mn;
            l *= cor;
            u64 cor2 = pk2(cor, cor);
            #pragma unroll
            for (int i = 0; i < 8; i++) acc2[i] = fmul2(acc2[i], cor2);

            #pragma unroll
            for (int j = 0; j < 8; j++) {
                if (j >= cc) break;
                float pe = __expf(s[j] - mn);
                l += pe;
                u64 pe2 = pk2(pe, pe);
                const u64* V2 = (const u64*)&Vs[kb + j][q4 * 16];
                #pragma unroll
                for (int i = 0; i < 8; i++) acc2[i] = ffma2(V2[i], pe2, acc2[i]);
            }
        }
        __syncthreads();
    }

    // write partials (un-normalized acc, plus m and l)
    long base = ((long)c * NHEAD + h) * SQ + q;
    if (q4 == 0) { g_pm[base] = m; g_pl[base] = l; }
    float* pa = g_pacc + base * HD + q4 * 16;
    #pragma unroll
    for (int i = 0; i < 8; i++) {
        float lo, hi;
        upk2(acc2[i], lo, hi);
        pa[2 * i]     = lo;
        pa[2 * i + 1] = hi;
    }
}

// Stage 2: exact log-sum-exp merge of <=NCH partials; emits bf16 split planes.
// grid (SQ, NHEAD), 64 threads (one per dim).
__global__ void attn_merge_k() {
    int q = blockIdx.x, h = blockIdx.y;
    int d = threadIdx.x;
    int nc = q / CHK + 1;

    __shared__ float vals[64];

    float m = -1e30f;
    for (int c = 0; c < nc; c++)
        m = fmaxf(m, g_pm[((long)c * NHEAD + h) * SQ + q]);
    float L = 0.f, o = 0.f;
    for (int c = 0; c < nc; c++) {
        long base = ((long)c * NHEAD + h) * SQ + q;
        float w = __expf(g_pm[base] - m);
        L += g_pl[base] * w;
        o += g_pacc[base * HD + d] * w;
    }
    vals[d] = o / L;
    __syncthreads();
    if (d < 32) {
        uint32_t hh, ll;
        bfsplit2(vals[2 * d], vals[2 * d + 1], hh, ll);
        long pidx = (long)q * 512 + h * 32 + d;
        g_attnh[pidx] = hh;
        g_attnl[pidx] = ll;
    }
}

// ---------------------------------------------------------------------------
__global__ void zero_cnt_k() { if (threadIdx.x < NEXP) g_ecnt[threadIdx.x] = 0; }

__global__ void router_k(const float* __restrict__ rw) {
    int tok = blockIdx.x, t = threadIdx.x;   // 128 threads
    __shared__ float sm[NEXP][128];
    __shared__ float logits[NEXP];
    const float* xr = g_ln + (long)tok * HID;

    for (int e = 0; e < NEXP; e++) {
        float s = 0.f;
        for (int j = t; j < HID; j += 128) s += xr[j] * rw[e * HID + j];
        sm[e][t] = s;
    }
    __syncthreads();
    if (t < NEXP) {
        float s = 0.f;
        for (int j = 0; j < 128; j++) s += sm[t][j];
        logits[t] = s;
    }
    __syncthreads();
    if (t == 0) {
        float mx = logits[0];
        for (int e = 1; e < NEXP; e++) mx = fmaxf(mx, logits[e]);
        float p[NEXP], den = 0.f;
        for (int e = 0; e < NEXP; e++) { p[e] = expf(logits[e] - mx); den += p[e]; }
        float idn = 1.f / den;
        for (int e = 0; e < NEXP; e++) p[e] *= idn;
        int i1 = 0;
        for (int e = 1; e < NEXP; e++) if (p[e] > p[i1]) i1 = e;
        int i2 = -1;
        for (int e = 0; e < NEXP; e++) {
            if (e == i1) continue;
            if (i2 < 0 || p[e] > p[i2]) i2 = e;
        }
        g_slotw[tok * 2 + 0] = p[i1];
        g_slotw[tok * 2 + 1] = p[i2];
        int p1 = atomicAdd(&g_ecnt[i1], 1); g_elist[i1 * SQ + p1] = tok * 2 + 0;
        int p2 = atomicAdd(&g_ecnt[i2], 1); g_elist[i2 * SQ + p2] = tok * 2 + 1;
    }
}

// ---------------------------------------------------------------------------
__global__ void combine_k() {
    int tok = blockIdx.x;
    float w0 = g_slotw[tok * 2 + 0];
    float w1 = g_slotw[tok * 2 + 1];
    const float* o0 = g_out2 + (long)(tok * 2 + 0) * HID;
    const float* o1 = g_out2 + (long)(tok * 2 + 1) * HID;
    float* xr = g_x + (long)tok * HID;
    for (int h = threadIdx.x; h < HID; h += blockDim.x)
        xr[h] += w0 * o0[h] + w1 * o1[h];
}

// ---------------------------------------------------------------------------
extern "C" void kernel_launch(void* const* d_in, const int* in_sizes, int n_in,
                              void* d_out, int out_size) {
    const int*   idx  = (const int*)  d_in[0];
    const float* tok  = (const float*)d_in[1];
    const float* pos  = (const float*)d_in[2];
    const float* ln1g = (const float*)d_in[3];
    const float* ln1b = (const float*)d_in[4];
    const float* wqkv = (const float*)d_in[5];
    const float* bqkv = (const float*)d_in[6];
    const float* wo   = (const float*)d_in[7];
    const float* bo   = (const float*)d_in[8];
    const float* ln2g = (const float*)d_in[9];
    const float* ln2b = (const float*)d_in[10];
    const float* rw   = (const float*)d_in[11];
    const float* w1   = (const float*)d_in[12];
    const float* w2   = (const float*)d_in[13];
    const float* lnfg = (const float*)d_in[14];
    const float* lnfb = (const float*)d_in[15];
    float* out = (float*)d_out;

    cudaFuncSetAttribute(bfgemm_k<0>, cudaFuncAttributeMaxDynamicSharedMemorySize, SM_TOT);
    cudaFuncSetAttribute(bfgemm_k<1>, cudaFuncAttributeMaxDynamicSharedMemorySize, SM_TOT);

    void* p_;
    #define SYM(var, sym) cudaGetSymbolAddress(&p_, sym); auto var = p_
    SYM(px_, g_x);        float* px = (float*)px_;
    SYM(pln_, g_ln);      float* pln = (float*)pln_;
    SYM(pqkv_, g_qkv);    float* pqkv = (float*)pqkv_;
    SYM(pout2_, g_out2);  float* pout2 = (float*)pout2_;
    SYM(pel_, g_elist);   const int* pel = (const int*)pel_;
    SYM(pec_, g_ecnt);    const int* pec = (const int*)pec_;
    SYM(pwqkvh_, g_wqkvh); uint32_t* pwqkvh = (uint32_t*)pwqkvh_;
    SYM(pwqkvl_, g_wqkvl); uint32_t* pwqkvl = (uint32_t*)pwqkvl_;
    SYM(pwoh_, g_woh);     uint32_t* pwoh = (uint32_t*)pwoh_;
    SYM(pwol_, g_wol);     uint32_t* pwol = (uint32_t*)pwol_;
    SYM(pw1h_, g_w1h);     uint32_t* pw1h = (uint32_t*)pw1h_;
    SYM(pw1l_, g_w1l);     uint32_t* pw1l = (uint32_t*)pw1l_;
    SYM(pw2h_, g_w2h);     uint32_t* pw2h = (uint32_t*)pw2h_;
    SYM(pw2l_, g_w2l);     uint32_t* pw2l = (uint32_t*)pw2l_;
    SYM(ptokh_, g_tokh);   uint32_t* ptokh = (uint32_t*)ptokh_;
    SYM(plnh_, g_lnh);     uint32_t* plnh = (uint32_t*)plnh_;
    SYM(plnl_, g_lnl);     uint32_t* plnl = (uint32_t*)plnl_;
    SYM(phidh_, g_hidh);   uint32_t* phidh = (uint32_t*)phidh_;
    SYM(phidl_, g_hidl);   uint32_t* phidl = (uint32_t*)phidl_;
    SYM(pattnh_, g_attnh); uint32_t* pattnh = (uint32_t*)pattnh_;
    SYM(pattnl_, g_attnl); uint32_t* pattnl = (uint32_t*)pattnl_;
    #undef SYM

    // ---- weight conversion ----
    {
        long tq = (long)NLAY * 3 * HID * HID / 2;
        conv_pack_k<<<(unsigned)((tq + 255) / 256), 256>>>(wqkv, pwqkvh, pwqkvl, tq);
        long tw = (long)NLAY * HID * HID / 2;
        conv_pack_k<<<(unsigned)((tw + 255) / 256), 256>>>(wo, pwoh, pwol, tw);
        long tt = (long)VOC * HID / 2;
        conv_pack_h_k<<<(unsigned)((tt + 255) / 256), 256>>>(tok, ptokh, tt);
        conv_tr_k<<<dim3(HID / 64, FFD / 32, NLAY * NEXP), 256>>>(
            w1, pw1h, pw1l, HID, FFD, (long)HID * FFD, (long)FFD * (HID / 2));
        conv_tr_k<<<dim3(FFD / 64, HID / 32, NLAY * NEXP), 256>>>(
            w2, pw2h, pw2l, FFD, HID, (long)FFD * HID, (long)HID * (FFD / 2));
    }

    embed_k<<<SQ, 256>>>(idx, tok, pos);

    for (int l = 0; l < NLAY; l++) {
        ln_k<<<SQ, 256>>>(px, pln, plnh, plnl, ln1g + l * HID, ln1b + l * HID, 0);
        bfgemm_k<0><<<dim3(24, 16, 1), 256, SM_TOT>>>(
            plnh, plnl, HID / 2,
            pwqkvh + (long)l * 3 * HID * (HID / 2), pwqkvl + (long)l * 3 * HID * (HID / 2), 0,
            bqkv + (long)l * 3 * HID,
            pqkv, 3 * HID, nullptr, nullptr, 0,
            SQ, 3 * HID, HID, 0, 0, 0, nullptr, nullptr);
        attn_part_k<<<dim3(SQ / 64, NHEAD, NCH), 256>>>();
        attn_merge_k<<<dim3(SQ, NHEAD), 64>>>();
        bfgemm_k<0><<<dim3(8, 16, 1), 256, SM_TOT>>>(
            pattnh, pattnl, HID / 2,
            pwoh + (long)l * HID * (HID / 2), pwol + (long)l * HID * (HID / 2), 0,
            bo + (long)l * HID,
            px, HID, nullptr, nullptr, 0,
            SQ, HID, HID, 1, 0, 0, nullptr, nullptr);
        ln_k<<<SQ, 256>>>(px, pln, plnh, plnl, ln2g + l * HID, ln2b + l * HID, 0);
        zero_cnt_k<<<1, 32>>>();
        router_k<<<SQ, 128>>>(rw + (long)l * NEXP * HID);
        bfgemm_k<0><<<dim3(FFD / 128, 16, NEXP), 256, SM_TOT>>>(
            plnh, plnl, HID / 2,
            pw1h + (long)l * NEXP * FFD * (HID / 2), pw1l + (long)l * NEXP * FFD * (HID / 2),
            (long)FFD * (HID / 2),
            nullptr,
            nullptr, 0, phidh, phidl, FFD / 2,
            SQ, FFD, HID, 0, 1, 1, pel, pec);
        bfgemm_k<0><<<dim3(HID / 128, 16, NEXP), 256, SM_TOT>>>(
            phidh, phidl, FFD / 2,
            pw2h + (long)l * NEXP * HID * (FFD / 2), pw2l + (long)l * NEXP * HID * (FFD / 2),
            (long)HID * (FFD / 2),
            nullptr,
            pout2, HID, nullptr, nullptr, 0,
            SQ, HID, FFD, 0, 0, 2, pel, pec);
        combine_k<<<SQ, 256>>>();
    }

    // final LN emits fp16 split planes; lm_head is 1-term fp16
    ln_k<<<SQ, 256>>>(px, pln, plnh, plnl, lnfg, lnfb, 1);
    bfgemm_k<1><<<dim3(VOC / 128, 16, 1), 256, SM_TOT>>>(
        plnh, plnl, HID / 2,
        ptokh, ptokh, 0,
        nullptr,
        out, VOC, nullptr, nullptr, 0,
        SQ, VOC, HID, 0, 0, 0, nullptr, nullptr);
}